// round 13
// baseline (speedup 1.0000x reference)
#include <cuda_runtime.h>
#include <cstdint>

// BiologicalNormalization: 3 chained per-row LayerNorms (D=512), gathered
// per-sample affine params; trailing sigmoid-gated blend is the identity.
//
// R13: per-warp cp.async (LDGSTS) pipeline, DEPTH=3 rows staged in smem.
// Loads decoupled from registers -> ~168KB/SM DRAM reads in flight
// (6x BW-latency product). Each thread copies exactly the float4 slots it
// later reads, so cp.async.wait_group alone gives visibility: no syncwarp,
// no block barriers. Compute body = R7 (72-reg cap, 28 warps/SM).

#define B_DIM 2048
#define S_DIM 128
#define D_DIM 512
#define THREADS 128
#define WARPS 4
#define WROWS 16          // rows per warp
#define DEPTH 3           // pipeline stages
#define RQ (D_DIM / 4)    // float4 per row = 128

__device__ __forceinline__ void cp16(uint32_t saddr, const void* gsrc) {
    asm volatile("cp.async.cg.shared.global [%0], [%1], 16;"
                 :: "r"(saddr), "l"(gsrc) : "memory");
}
__device__ __forceinline__ void cp_commit() {
    asm volatile("cp.async.commit_group;" ::: "memory");
}
__device__ __forceinline__ void cp_wait_all_but_2() {
    asm volatile("cp.async.wait_group 2;" ::: "memory");
}

__global__ __launch_bounds__(THREADS, 7)
void bionorm_kernel(const float* __restrict__ x,
                    const int* __restrict__ pathway_ids,
                    const int* __restrict__ compartment_ids,
                    const int* __restrict__ cell_type_ids,
                    const float* __restrict__ pg, const float* __restrict__ pb,
                    const float* __restrict__ cg, const float* __restrict__ cb,
                    const float* __restrict__ tg, const float* __restrict__ tb,
                    float* __restrict__ out)
{
    // [warp][stage][float4 slot]; 4*3*2KB = 24KB.
    __shared__ float4 buf[WARPS][DEPTH][RQ];

    const int blk = blockIdx.x;
    const int b = blk >> 1;           // sample
    const int half = blk & 1;         // 64-row half of the sample
    const int warp = threadIdx.x >> 5;
    const int lane = threadIdx.x & 31;

    const int p_id = __ldg(pathway_ids + b);
    const int c_id = __ldg(compartment_ids + b);
    const int t_id = __ldg(cell_type_ids + b);

    const size_t row0 = (size_t)b * S_DIM + half * 64 + warp * WROWS;
    const float4* __restrict__ xbase =
        reinterpret_cast<const float4*>(x) + row0 * RQ + lane;
    float4* __restrict__ obase =
        reinterpret_cast<float4*>(out) + row0 * RQ + lane;

    // This thread's smem slots: stage stride 2048B, slot stride 512B.
    const uint32_t s0 =
        (uint32_t)__cvta_generic_to_shared(&buf[warp][0][lane]);

    // Prologue: stage rows 0..DEPTH-1.
    #pragma unroll
    for (int d = 0; d < DEPTH; d++) {
        const float4* src = xbase + (size_t)d * RQ;
        #pragma unroll
        for (int i = 0; i < 4; i++)
            cp16(s0 + d * 2048 + i * 512, src + 32 * i);
        cp_commit();
    }

    const float inv_d = 1.0f / (float)D_DIM;
    const float eps = 1e-5f;

    int st = 0;                        // stage of row r
    for (int r = 0; r < WROWS; r++) {
        cp_wait_all_but_2();           // oldest group (row r) complete

        // Read this thread's own-copied slots (no cross-thread visibility
        // needed).
        float4 v[4];
        #pragma unroll
        for (int i = 0; i < 4; i++)
            v[i] = buf[warp][st][lane + 32 * i];

        #pragma unroll
        for (int p = 0; p < 3; p++) {
            const float4* gvp;
            const float4* bvp;
            if (p == 0) {
                gvp = reinterpret_cast<const float4*>(pg + (size_t)p_id * D_DIM);
                bvp = reinterpret_cast<const float4*>(pb + (size_t)p_id * D_DIM);
            } else if (p == 1) {
                gvp = reinterpret_cast<const float4*>(cg + (size_t)c_id * D_DIM);
                bvp = reinterpret_cast<const float4*>(cb + (size_t)c_id * D_DIM);
            } else {
                gvp = reinterpret_cast<const float4*>(tg + (size_t)t_id * D_DIM);
                bvp = reinterpret_cast<const float4*>(tb + (size_t)t_id * D_DIM);
            }

            float s = 0.f, q = 0.f;
            #pragma unroll
            for (int i = 0; i < 4; i++) {
                s += v[i].x + v[i].y + v[i].z + v[i].w;
                q = fmaf(v[i].x, v[i].x, q);
                q = fmaf(v[i].y, v[i].y, q);
                q = fmaf(v[i].z, v[i].z, q);
                q = fmaf(v[i].w, v[i].w, q);
            }
            #pragma unroll
            for (int o = 16; o > 0; o >>= 1) {
                s += __shfl_xor_sync(0xffffffffu, s, o);
                q += __shfl_xor_sync(0xffffffffu, q, o);
            }

            const float mean = s * inv_d;
            const float var = fmaf(-mean, mean, q * inv_d);
            const float a = rsqrtf(var + eps);
            const float c = -mean * a;

            #pragma unroll
            for (int i = 0; i < 4; i++) {
                const float4 gg = __ldg(gvp + lane + 32 * i);
                const float4 bb = __ldg(bvp + lane + 32 * i);
                v[i].x = fmaf(fmaf(v[i].x, a, c), gg.x, bb.x);
                v[i].y = fmaf(fmaf(v[i].y, a, c), gg.y, bb.y);
                v[i].z = fmaf(fmaf(v[i].z, a, c), gg.z, bb.z);
                v[i].w = fmaf(fmaf(v[i].w, a, c), gg.w, bb.w);
            }
        }

        float4* orow = obase + (size_t)r * RQ;
        #pragma unroll
        for (int i = 0; i < 4; i++)
            orow[32 * i] = v[i];

        // Refill this stage with row r+DEPTH (if any); always commit so the
        // tail wait_group accounting stays correct (empty groups are legal).
        if (r + DEPTH < WROWS) {
            const float4* src = xbase + (size_t)(r + DEPTH) * RQ;
            #pragma unroll
            for (int i = 0; i < 4; i++)
                cp16(s0 + st * 2048 + i * 512, src + 32 * i);
        }
        cp_commit();

        st = (st == DEPTH - 1) ? 0 : st + 1;
    }
}

extern "C" void kernel_launch(void* const* d_in, const int* in_sizes, int n_in,
                              void* d_out, int out_size)
{
    const float* x  = (const float*)d_in[0];
    const int* pid  = (const int*)d_in[1];
    const int* cid  = (const int*)d_in[2];
    const int* tid  = (const int*)d_in[3];
    const float* pg = (const float*)d_in[4];
    const float* pb = (const float*)d_in[5];
    const float* cg = (const float*)d_in[6];
    const float* cb = (const float*)d_in[7];
    const float* tg = (const float*)d_in[8];
    const float* tb = (const float*)d_in[9];
    // d_in[10] = W, d_in[11] = b : unused (gated blend is the identity)
    float* out = (float*)d_out;

    // 262144 rows / (4 warps * 16 rows) = 4096 blocks (2 per sample).
    dim3 grid(B_DIM * 2);
    dim3 block(THREADS);
    bionorm_kernel<<<grid, block>>>(x, pid, cid, tid,
                                    pg, pb, cg, cb, tg, tb, out);
}

// round 14
// speedup vs baseline: 1.5484x; 1.5484x over previous
#include <cuda_runtime.h>

// BiologicalNormalization: 3 chained per-row LayerNorms (D=512), gathered
// per-sample affine params; trailing sigmoid-gated blend is the identity.
//
// R14: R12 compute body (ROWS=2/warp, 128 thr, lb(128,7) -> 72 regs,
// 28 warps/SM, warp-local shuffle reductions, __ldcg streaming x) but ONE
// BLOCK PER SAMPLE: 2048 blocks, each loops over 16 chunks of 8 rows.
// Ids load once per block; params stay L1-hot across 16 reuses; per-chunk
// prologue collapses to an address increment; loop lets ptxas overlap next
// chunk's loads with current store tail.

#define B_DIM 2048
#define S_DIM 128
#define D_DIM 512
#define THREADS 128
#define WARPS 4
#define ROWS 2            // rows per warp -> 8 rows per iteration
#define ITERS (S_DIM / (WARPS * ROWS))   // 16

__global__ __launch_bounds__(THREADS, 7)
void bionorm_kernel(const float* __restrict__ x,
                    const int* __restrict__ pathway_ids,
                    const int* __restrict__ compartment_ids,
                    const int* __restrict__ cell_type_ids,
                    const float* __restrict__ pg, const float* __restrict__ pb,
                    const float* __restrict__ cg, const float* __restrict__ cb,
                    const float* __restrict__ tg, const float* __restrict__ tb,
                    float* __restrict__ out)
{
    const int b = blockIdx.x;         // sample
    const int lane = threadIdx.x & 31;

    const int p_id = __ldg(pathway_ids + b);
    const int c_id = __ldg(compartment_ids + b);
    const int t_id = __ldg(cell_type_ids + b);

    const float inv_d = 1.0f / (float)D_DIM;
    const float eps = 1e-5f;

    // This warp's first group: rows warp*2, advancing by 8 rows per iter.
    size_t elem = ((size_t)b * S_DIM + (threadIdx.x >> 5) * ROWS) * D_DIM;

    for (int it = 0; it < ITERS; it++) {
        const float4* __restrict__ xr =
            reinterpret_cast<const float4*>(x + elem);

        // Front-batched load of 2 full rows: 8 independent LDG.128.CG.
        float4 v[ROWS][4];
        #pragma unroll
        for (int r = 0; r < ROWS; r++)
            #pragma unroll
            for (int i = 0; i < 4; i++)
                v[r][i] = __ldcg(xr + r * (D_DIM / 4) + lane + 32 * i);

        #pragma unroll
        for (int p = 0; p < 3; p++) {
            // Param pointers rematerialized per pass (ids stay in regs;
            // lines stay hot in L1 across all 16 iterations).
            const float4* gvp;
            const float4* bvp;
            if (p == 0) {
                gvp = reinterpret_cast<const float4*>(pg + (size_t)p_id * D_DIM);
                bvp = reinterpret_cast<const float4*>(pb + (size_t)p_id * D_DIM);
            } else if (p == 1) {
                gvp = reinterpret_cast<const float4*>(cg + (size_t)c_id * D_DIM);
                bvp = reinterpret_cast<const float4*>(cb + (size_t)c_id * D_DIM);
            } else {
                gvp = reinterpret_cast<const float4*>(tg + (size_t)t_id * D_DIM);
                bvp = reinterpret_cast<const float4*>(tb + (size_t)t_id * D_DIM);
            }

            float sum[ROWS], sq[ROWS];
            #pragma unroll
            for (int r = 0; r < ROWS; r++) {
                float s = 0.f, q = 0.f;
                #pragma unroll
                for (int i = 0; i < 4; i++) {
                    s += v[r][i].x + v[r][i].y + v[r][i].z + v[r][i].w;
                    q = fmaf(v[r][i].x, v[r][i].x, q);
                    q = fmaf(v[r][i].y, v[r][i].y, q);
                    q = fmaf(v[r][i].z, v[r][i].z, q);
                    q = fmaf(v[r][i].w, v[r][i].w, q);
                }
                sum[r] = s; sq[r] = q;
            }
            #pragma unroll
            for (int o = 16; o > 0; o >>= 1) {
                #pragma unroll
                for (int r = 0; r < ROWS; r++) {
                    sum[r] += __shfl_xor_sync(0xffffffffu, sum[r], o);
                    sq[r]  += __shfl_xor_sync(0xffffffffu, sq[r],  o);
                }
            }

            float a[ROWS], c[ROWS];
            #pragma unroll
            for (int r = 0; r < ROWS; r++) {
                const float mean = sum[r] * inv_d;
                const float var = fmaf(-mean, mean, sq[r] * inv_d);
                a[r] = rsqrtf(var + eps);
                c[r] = -mean * a[r];
            }

            #pragma unroll
            for (int i = 0; i < 4; i++) {
                const float4 gg = __ldg(gvp + lane + 32 * i);
                const float4 bb = __ldg(bvp + lane + 32 * i);
                #pragma unroll
                for (int r = 0; r < ROWS; r++) {
                    v[r][i].x = fmaf(fmaf(v[r][i].x, a[r], c[r]), gg.x, bb.x);
                    v[r][i].y = fmaf(fmaf(v[r][i].y, a[r], c[r]), gg.y, bb.y);
                    v[r][i].z = fmaf(fmaf(v[r][i].z, a[r], c[r]), gg.z, bb.z);
                    v[r][i].w = fmaf(fmaf(v[r][i].w, a[r], c[r]), gg.w, bb.w);
                }
            }
        }

        float4* __restrict__ orow = reinterpret_cast<float4*>(out + elem);
        #pragma unroll
        for (int r = 0; r < ROWS; r++)
            #pragma unroll
            for (int i = 0; i < 4; i++)
                orow[r * (D_DIM / 4) + lane + 32 * i] = v[r][i];

        elem += (size_t)(WARPS * ROWS) * D_DIM;   // next 8-row chunk
    }
}

extern "C" void kernel_launch(void* const* d_in, const int* in_sizes, int n_in,
                              void* d_out, int out_size)
{
    const float* x  = (const float*)d_in[0];
    const int* pid  = (const int*)d_in[1];
    const int* cid  = (const int*)d_in[2];
    const int* tid  = (const int*)d_in[3];
    const float* pg = (const float*)d_in[4];
    const float* pb = (const float*)d_in[5];
    const float* cg = (const float*)d_in[6];
    const float* cb = (const float*)d_in[7];
    const float* tg = (const float*)d_in[8];
    const float* tb = (const float*)d_in[9];
    // d_in[10] = W, d_in[11] = b : unused (gated blend is the identity)
    float* out = (float*)d_out;

    dim3 grid(B_DIM);        // one block per sample
    dim3 block(THREADS);
    bionorm_kernel<<<grid, block>>>(x, pid, cid, tid,
                                    pg, pb, cg, cb, tg, tb, out);
}

// round 15
// speedup vs baseline: 1.6850x; 1.0882x over previous
#include <cuda_runtime.h>

// BiologicalNormalization: 3 chained per-row LayerNorms (D=512), gathered
// per-sample affine params; trailing sigmoid-gated blend is the identity.
//
// R15: R12 body (ROWS=2/warp one-shot groups, warp-local reductions,
// __ldcg streaming x, remat'd param pointers) at the 30-warp/SM point:
// 96-thread blocks, __launch_bounds__(96,10) -> 68-reg cap, 960 thr/SM.
// Flat group indexing (shifts only) decouples block shape from sample
// structure; 2-row groups never straddle a sample (128 rows/sample, even).

#define B_DIM 2048
#define S_DIM 128
#define D_DIM 512
#define THREADS 96
#define WPB 3                 // warps per block
#define TOTAL_GROUPS ((B_DIM * S_DIM) / 2)   // 131072 two-row groups

__global__ __launch_bounds__(THREADS, 10)
void bionorm_kernel(const float* __restrict__ x,
                    const int* __restrict__ pathway_ids,
                    const int* __restrict__ compartment_ids,
                    const int* __restrict__ cell_type_ids,
                    const float* __restrict__ pg, const float* __restrict__ pb,
                    const float* __restrict__ cg, const float* __restrict__ cb,
                    const float* __restrict__ tg, const float* __restrict__ tb,
                    float* __restrict__ out)
{
    const int group = blockIdx.x * WPB + (threadIdx.x >> 5);
    if (group >= TOTAL_GROUPS) return;
    const int lane = threadIdx.x & 31;

    const int row0 = group << 1;          // first of this warp's 2 rows
    const int b = row0 >> 7;              // sample (S_DIM = 128)

    const int p_id = __ldg(pathway_ids + b);
    const int c_id = __ldg(compartment_ids + b);
    const int t_id = __ldg(cell_type_ids + b);

    const size_t elem0 = (size_t)row0 * D_DIM;
    const float4* __restrict__ xr = reinterpret_cast<const float4*>(x + elem0);

    // Front-batched load of 2 full rows: 8 independent LDG.128.CG.
    float4 v[2][4];
    #pragma unroll
    for (int r = 0; r < 2; r++)
        #pragma unroll
        for (int i = 0; i < 4; i++)
            v[r][i] = __ldcg(xr + r * (D_DIM / 4) + lane + 32 * i);

    const float inv_d = 1.0f / (float)D_DIM;
    const float eps = 1e-5f;

    #pragma unroll
    for (int p = 0; p < 3; p++) {
        // Param pointers rematerialized per pass from constant-bank bases.
        const float4* gvp;
        const float4* bvp;
        if (p == 0) {
            gvp = reinterpret_cast<const float4*>(pg + (size_t)p_id * D_DIM);
            bvp = reinterpret_cast<const float4*>(pb + (size_t)p_id * D_DIM);
        } else if (p == 1) {
            gvp = reinterpret_cast<const float4*>(cg + (size_t)c_id * D_DIM);
            bvp = reinterpret_cast<const float4*>(cb + (size_t)c_id * D_DIM);
        } else {
            gvp = reinterpret_cast<const float4*>(tg + (size_t)t_id * D_DIM);
            bvp = reinterpret_cast<const float4*>(tb + (size_t)t_id * D_DIM);
        }

        float sum[2], sq[2];
        #pragma unroll
        for (int r = 0; r < 2; r++) {
            float s = 0.f, q = 0.f;
            #pragma unroll
            for (int i = 0; i < 4; i++) {
                s += v[r][i].x + v[r][i].y + v[r][i].z + v[r][i].w;
                q = fmaf(v[r][i].x, v[r][i].x, q);
                q = fmaf(v[r][i].y, v[r][i].y, q);
                q = fmaf(v[r][i].z, v[r][i].z, q);
                q = fmaf(v[r][i].w, v[r][i].w, q);
            }
            sum[r] = s; sq[r] = q;
        }
        #pragma unroll
        for (int o = 16; o > 0; o >>= 1) {
            #pragma unroll
            for (int r = 0; r < 2; r++) {
                sum[r] += __shfl_xor_sync(0xffffffffu, sum[r], o);
                sq[r]  += __shfl_xor_sync(0xffffffffu, sq[r],  o);
            }
        }

        // a = rstd, c = -mean*rstd  ->  normalized = fma(v, a, c)
        float a[2], c[2];
        #pragma unroll
        for (int r = 0; r < 2; r++) {
            const float mean = sum[r] * inv_d;
            const float var = fmaf(-mean, mean, sq[r] * inv_d);
            a[r] = rsqrtf(var + eps);
            c[r] = -mean * a[r];
        }

        #pragma unroll
        for (int i = 0; i < 4; i++) {
            const float4 gg = __ldg(gvp + lane + 32 * i);
            const float4 bb = __ldg(bvp + lane + 32 * i);
            #pragma unroll
            for (int r = 0; r < 2; r++) {
                v[r][i].x = fmaf(fmaf(v[r][i].x, a[r], c[r]), gg.x, bb.x);
                v[r][i].y = fmaf(fmaf(v[r][i].y, a[r], c[r]), gg.y, bb.y);
                v[r][i].z = fmaf(fmaf(v[r][i].z, a[r], c[r]), gg.z, bb.z);
                v[r][i].w = fmaf(fmaf(v[r][i].w, a[r], c[r]), gg.w, bb.w);
            }
        }
    }

    float4* __restrict__ orow = reinterpret_cast<float4*>(out + elem0);
    #pragma unroll
    for (int r = 0; r < 2; r++)
        #pragma unroll
        for (int i = 0; i < 4; i++)
            orow[r * (D_DIM / 4) + lane + 32 * i] = v[r][i];
}

extern "C" void kernel_launch(void* const* d_in, const int* in_sizes, int n_in,
                              void* d_out, int out_size)
{
    const float* x  = (const float*)d_in[0];
    const int* pid  = (const int*)d_in[1];
    const int* cid  = (const int*)d_in[2];
    const int* tid  = (const int*)d_in[3];
    const float* pg = (const float*)d_in[4];
    const float* pb = (const float*)d_in[5];
    const float* cg = (const float*)d_in[6];
    const float* cb = (const float*)d_in[7];
    const float* tg = (const float*)d_in[8];
    const float* tb = (const float*)d_in[9];
    // d_in[10] = W, d_in[11] = b : unused (gated blend is the identity)
    float* out = (float*)d_out;

    const int grid = (TOTAL_GROUPS + WPB - 1) / WPB;   // 43691
    bionorm_kernel<<<grid, THREADS>>>(x, pid, cid, tid,
                                      pg, pb, cg, cb, tg, tb, out);
}

// round 16
// speedup vs baseline: 1.7397x; 1.0325x over previous
#include <cuda_runtime.h>

// BiologicalNormalization: 3 chained per-row LayerNorms (D=512), gathered
// per-sample affine params; trailing sigmoid-gated blend is the identity.
//
// R16: R7 config (ROWS=2/warp, 128 thr, lb(128,7) -> 72 regs, 28 warps/SM,
// full-warp shuffle reductions, remat'd param pointers) + pass-0 gamma/beta
// partially prefetched into the front load batch so the first normalize
// doesn't wait on an L2-latency param fetch after the reduction.

#define B_DIM 2048
#define S_DIM 128
#define D_DIM 512
#define THREADS 128
#define WARPS 4
#define ROWS 2            // rows per warp -> 8 rows per block
#define SPLIT 16          // blocks per sample

__global__ __launch_bounds__(THREADS, 7)
void bionorm_kernel(const float* __restrict__ x,
                    const int* __restrict__ pathway_ids,
                    const int* __restrict__ compartment_ids,
                    const int* __restrict__ cell_type_ids,
                    const float* __restrict__ pg, const float* __restrict__ pb,
                    const float* __restrict__ cg, const float* __restrict__ cb,
                    const float* __restrict__ tg, const float* __restrict__ tb,
                    float* __restrict__ out)
{
    const int blk = blockIdx.x;
    const int b = blk >> 4;           // sample
    const int lane = threadIdx.x & 31;

    const int p_id = __ldg(pathway_ids + b);
    const int c_id = __ldg(compartment_ids + b);
    const int t_id = __ldg(cell_type_ids + b);

    const size_t elem0 = ((size_t)b * S_DIM
                        + ((blk & 15) * (WARPS * ROWS) + (threadIdx.x >> 5) * ROWS))
                        * D_DIM;
    const float4* __restrict__ xr = reinterpret_cast<const float4*>(x + elem0);

    // Front-batched load of 2 full rows: 8 independent LDG.128.
    float4 v[ROWS][4];
    #pragma unroll
    for (int r = 0; r < ROWS; r++)
        #pragma unroll
        for (int i = 0; i < 4; i++)
            v[r][i] = xr[r * (D_DIM / 4) + lane + 32 * i];

    // Prefetch the first half of pass-0 params alongside the x loads
    // (independent; covers the L2 latency behind the stats phase).
    const float4* __restrict__ g0 =
        reinterpret_cast<const float4*>(pg + (size_t)p_id * D_DIM);
    const float4* __restrict__ b0 =
        reinterpret_cast<const float4*>(pb + (size_t)p_id * D_DIM);
    float4 pgg[2], pbb[2];
    #pragma unroll
    for (int i = 0; i < 2; i++) {
        pgg[i] = __ldg(g0 + lane + 32 * i);
        pbb[i] = __ldg(b0 + lane + 32 * i);
    }

    const float inv_d = 1.0f / (float)D_DIM;
    const float eps = 1e-5f;

    #pragma unroll
    for (int p = 0; p < 3; p++) {
        // Param pointers rematerialized per pass from constant-bank bases.
        const float4* gvp;
        const float4* bvp;
        if (p == 0) {
            gvp = g0;
            bvp = b0;
        } else if (p == 1) {
            gvp = reinterpret_cast<const float4*>(cg + (size_t)c_id * D_DIM);
            bvp = reinterpret_cast<const float4*>(cb + (size_t)c_id * D_DIM);
        } else {
            gvp = reinterpret_cast<const float4*>(tg + (size_t)t_id * D_DIM);
            bvp = reinterpret_cast<const float4*>(tb + (size_t)t_id * D_DIM);
        }

        float sum[ROWS], sq[ROWS];
        #pragma unroll
        for (int r = 0; r < ROWS; r++) {
            float s = 0.f, q = 0.f;
            #pragma unroll
            for (int i = 0; i < 4; i++) {
                s += v[r][i].x + v[r][i].y + v[r][i].z + v[r][i].w;
                q = fmaf(v[r][i].x, v[r][i].x, q);
                q = fmaf(v[r][i].y, v[r][i].y, q);
                q = fmaf(v[r][i].z, v[r][i].z, q);
                q = fmaf(v[r][i].w, v[r][i].w, q);
            }
            sum[r] = s; sq[r] = q;
        }
        #pragma unroll
        for (int o = 16; o > 0; o >>= 1) {
            #pragma unroll
            for (int r = 0; r < ROWS; r++) {
                sum[r] += __shfl_xor_sync(0xffffffffu, sum[r], o);
                sq[r]  += __shfl_xor_sync(0xffffffffu, sq[r],  o);
            }
        }

        // a = rstd, c = -mean*rstd  ->  normalized = fma(v, a, c)
        float a[ROWS], c[ROWS];
        #pragma unroll
        for (int r = 0; r < ROWS; r++) {
            const float mean = sum[r] * inv_d;
            const float var = fmaf(-mean, mean, sq[r] * inv_d);
            a[r] = rsqrtf(var + eps);
            c[r] = -mean * a[r];
        }

        #pragma unroll
        for (int i = 0; i < 4; i++) {
            const float4 gg = (p == 0 && i < 2) ? pgg[i]
                            : __ldg(gvp + lane + 32 * i);
            const float4 bb = (p == 0 && i < 2) ? pbb[i]
                            : __ldg(bvp + lane + 32 * i);
            #pragma unroll
            for (int r = 0; r < ROWS; r++) {
                v[r][i].x = fmaf(fmaf(v[r][i].x, a[r], c[r]), gg.x, bb.x);
                v[r][i].y = fmaf(fmaf(v[r][i].y, a[r], c[r]), gg.y, bb.y);
                v[r][i].z = fmaf(fmaf(v[r][i].z, a[r], c[r]), gg.z, bb.z);
                v[r][i].w = fmaf(fmaf(v[r][i].w, a[r], c[r]), gg.w, bb.w);
            }
        }
    }

    float4* __restrict__ orow = reinterpret_cast<float4*>(out + elem0);
    #pragma unroll
    for (int r = 0; r < ROWS; r++)
        #pragma unroll
        for (int i = 0; i < 4; i++)
            orow[r * (D_DIM / 4) + lane + 32 * i] = v[r][i];
}

extern "C" void kernel_launch(void* const* d_in, const int* in_sizes, int n_in,
                              void* d_out, int out_size)
{
    const float* x  = (const float*)d_in[0];
    const int* pid  = (const int*)d_in[1];
    const int* cid  = (const int*)d_in[2];
    const int* tid  = (const int*)d_in[3];
    const float* pg = (const float*)d_in[4];
    const float* pb = (const float*)d_in[5];
    const float* cg = (const float*)d_in[6];
    const float* cb = (const float*)d_in[7];
    const float* tg = (const float*)d_in[8];
    const float* tb = (const float*)d_in[9];
    // d_in[10] = W, d_in[11] = b : unused (gated blend is the identity)
    float* out = (float*)d_out;

    dim3 grid(B_DIM * SPLIT);
    dim3 block(THREADS);
    bionorm_kernel<<<grid, block>>>(x, pid, cid, tid,
                                    pg, pb, cg, cb, tg, tb, out);
}